// round 12
// baseline (speedup 1.0000x reference)
#include <cuda_runtime.h>
#include <cstdint>
#include <math.h>

#define BVAL 16
#define HVAL 256
#define NODES0 65536

// ---------------- device scratch ----------------
__device__ __align__(16) float g_bufA_h[(size_t)NODES0 * HVAL];
__device__ __align__(16) float g_bufA_c[(size_t)NODES0 * HVAL];
__device__ __align__(16) float g_bufB_h[(size_t)(NODES0 / 2) * HVAL];
__device__ __align__(16) float g_bufB_c[(size_t)(NODES0 / 2) * HVAL];
// g_Wk chunk images: [kc(16)][r(16)=ks*4+qc][p(1280)][pair(2)]; pair=(k, k+4), k=kc*32+ks*8+qc
__device__ __align__(16) float g_Wk[(size_t)16 * 16 * 1280 * 2];
// g_WpK flat [k(256)][n(256)], tf32-RN
__device__ __align__(16) float g_WpK[(size_t)256 * 256];
__device__ __align__(16) float g_bt[1280];                  // packed gate biases

__device__ unsigned g_bar_cnt = 0;
__device__ unsigned g_bar_gen = 0;

// ---------------- helpers ----------------
__device__ __forceinline__ float rnd_tf32(float x) {
    uint32_t r;
    asm("cvt.rna.tf32.f32 %0, %1;" : "=r"(r) : "f"(x));
    return __uint_as_float(r);
}
__device__ __forceinline__ float sigm(float x) { return 1.0f / (1.0f + __expf(-x)); }

__device__ __forceinline__ void cp16(void* dst, const float* src) {
    uint32_t d = (uint32_t)__cvta_generic_to_shared(dst);
    asm volatile("cp.async.cg.shared.global [%0], [%1], 16;"
                 :: "r"(d), "l"(__cvta_generic_to_global(src)));
}
#define CP_COMMIT() asm volatile("cp.async.commit_group;" ::: "memory")
#define CP_WAIT1()  asm volatile("cp.async.wait_group 1;" ::: "memory")
#define CP_WAIT0()  asm volatile("cp.async.wait_group 0;" ::: "memory")

__device__ __forceinline__ void mma_tf32(float* c, const uint32_t* a, uint32_t b0, uint32_t b1) {
    asm volatile("mma.sync.aligned.m16n8k8.row.col.f32.tf32.tf32.f32 "
                 "{%0,%1,%2,%3}, {%4,%5,%6,%7}, {%8,%9}, {%0,%1,%2,%3};"
                 : "+f"(c[0]), "+f"(c[1]), "+f"(c[2]), "+f"(c[3])
                 : "r"(a[0]), "r"(a[1]), "r"(a[2]), "r"(a[3]), "r"(b0), "r"(b1));
}

// ---------------- pack kernel (weights only) ----------------
__global__ void pack_weights(const float* __restrict__ Wp,
                             const float* __restrict__ Wfl, const float* __restrict__ Wfr,
                             const float* __restrict__ Wi,  const float* __restrict__ Wo,
                             const float* __restrict__ Wc,
                             const float* __restrict__ bfl, const float* __restrict__ bfr,
                             const float* __restrict__ bi,  const float* __restrict__ bo,
                             const float* __restrict__ bc) {
    int idx = blockIdx.x * blockDim.x + threadIdx.x;
    int stride = gridDim.x * blockDim.x;
    for (int i = idx; i < 16 * 16 * 1280 * 2; i += stride) {
        int e = i & 1;
        int t = i >> 1;
        int p = t % 1280;
        int rr = t / 1280;
        int r = rr & 15, kc = rr >> 4;
        int k = kc * 32 + (r >> 2) * 8 + (r & 3) + e * 4;
        int grp = p / 160, rem = p - grp * 160;
        int g5 = rem >> 5, jj = rem & 31;
        const float* W = (g5 == 0) ? Wfl : (g5 == 1) ? Wfr : (g5 == 2) ? Wi : (g5 == 3) ? Wo : Wc;
        g_Wk[i] = rnd_tf32(W[k * 256 + grp * 32 + jj]);
    }
    for (int i = idx; i < 256 * 256; i += stride) g_WpK[i] = rnd_tf32(Wp[i]);
    for (int i = idx; i < 1280; i += stride) {
        int grp = i / 160, rem = i - grp * 160;
        int g5 = rem >> 5, jj = rem & 31;
        const float* bb = (g5 == 0) ? bfl : (g5 == 1) ? bfr : (g5 == 2) ? bi : (g5 == 3) ? bo : bc;
        g_bt[i] = bb[grp * 32 + jj];
    }
}

// ================= LEVEL KERNEL (big levels) — unchanged from R11 =================
#define ASTR 36
#define BSTR2 328
#define LV_AF (128 * ASTR)          // 4608
#define LV_BF (16 * BSTR2)          // 5248
#define LV_STGF (LV_AF + LV_BF)     // 9856
#define LV_SMEM (2 * LV_STGF * 4)   // 78848

__global__ __launch_bounds__(256, 2) void level_fused(const float* __restrict__ Hin,
                                                      const float* __restrict__ Cin,
                                                      float* __restrict__ Hout,
                                                      float* __restrict__ Cout, int Mout) {
    extern __shared__ float dsm[];
    __shared__ float s_bias[160];
    const int tid = threadIdx.x, wid = tid >> 5, lane = tid & 31;
    const int qr = lane >> 2, qc = lane & 3;
    const int wm = wid >> 1, wn = wid & 1;
    const int mBase = blockIdx.x * 128;
    const int grp = blockIdx.y;
    const int p0 = grp * 160, c0 = grp * 32;

    for (int i = tid; i < 160; i += 256) s_bias[i] = g_bt[p0 + i];

    float acc[2][10][4];
#pragma unroll
    for (int a = 0; a < 2; a++)
#pragma unroll
        for (int b = 0; b < 10; b++)
#pragma unroll
            for (int e = 0; e < 4; e++) acc[a][b][e] = 0.f;

    auto load_chunk = [&](int kc) {
        float* As = dsm + (kc & 1) * LV_STGF;
        float* Bs = As + LV_AF;
#pragma unroll
        for (int t = 0; t < 4; t++) {
            int v = tid + t * 256;
            int r = v >> 3, c = v & 7;
            int row = mBase + r; if (row >= Mout) row = Mout - 1;
            cp16(As + r * ASTR + c * 4, Hin + (size_t)row * 512 + kc * 32 + c * 4);
        }
#pragma unroll
        for (int t = 0; t < 5; t++) {
            int v = tid + t * 256;
            int kr = v / 80, c4 = v - kr * 80;
            cp16(Bs + kr * BSTR2 + c4 * 4,
                 g_Wk + (size_t)(kc * 16 + kr) * 2560 + p0 * 2 + c4 * 4);
        }
        CP_COMMIT();
    };

    load_chunk(0);
    for (int i = 0; i < 16; i++) {
        if (i + 1 < 16) { load_chunk(i + 1); CP_WAIT1(); } else { CP_WAIT0(); }
        __syncthreads();
        const float* As = dsm + (i & 1) * LV_STGF;
        const float* Bs = As + LV_AF;
#pragma unroll
        for (int ks = 0; ks < 4; ks++) {
            uint32_t a[2][4];
#pragma unroll
            for (int ma = 0; ma < 2; ma++) {
                const float* ap = As + (wm * 32 + ma * 16 + qr) * ASTR + ks * 8 + qc;
                a[ma][0] = __float_as_uint(ap[0]);
                a[ma][1] = __float_as_uint(ap[8 * ASTR]);
                a[ma][2] = __float_as_uint(ap[4]);
                a[ma][3] = __float_as_uint(ap[8 * ASTR + 4]);
            }
            const float* brow = Bs + (ks * 4 + qc) * BSTR2;
#pragma unroll
            for (int na = 0; na < 10; na++) {
                int col = (na >> 1) * 32 + wn * 16 + (na & 1) * 8 + qr;
                float2 bf = *(const float2*)(brow + col * 2);
                uint32_t b0 = __float_as_uint(bf.x);
                uint32_t b1 = __float_as_uint(bf.y);
                mma_tf32(acc[0][na], a[0], b0, b1);
                mma_tf32(acc[1][na], a[1], b0, b1);
            }
        }
        __syncthreads();
    }

#pragma unroll
    for (int ma = 0; ma < 2; ma++) {
#pragma unroll
        for (int eh = 0; eh < 2; eh++) {
            int row = mBase + wm * 32 + ma * 16 + qr + eh * 8;
            if (row < Mout) {
#pragma unroll
                for (int na = 0; na < 2; na++) {
                    int jj = wn * 16 + na * 8 + qc * 2;
                    float2 cl = *(const float2*)(Cin + (size_t)row * 512 + c0 + jj);
                    float2 cr = *(const float2*)(Cin + (size_t)row * 512 + 256 + c0 + jj);
                    float hv[2], cv[2];
#pragma unroll
                    for (int e = 0; e < 2; e++) {
                        int bi_ = jj + e;
                        float fl = sigm(acc[ma][0 * 2 + na][eh * 2 + e] + s_bias[0 * 32 + bi_]);
                        float fr = sigm(acc[ma][1 * 2 + na][eh * 2 + e] + s_bias[1 * 32 + bi_]);
                        float ig = sigm(acc[ma][2 * 2 + na][eh * 2 + e] + s_bias[2 * 32 + bi_]);
                        float og = sigm(acc[ma][3 * 2 + na][eh * 2 + e] + s_bias[3 * 32 + bi_]);
                        float cc = tanhf(acc[ma][4 * 2 + na][eh * 2 + e] + s_bias[4 * 32 + bi_]);
                        float clv = (e == 0) ? cl.x : cl.y;
                        float crv = (e == 0) ? cr.x : cr.y;
                        float cn = fl * clv + fr * crv + ig * cc;
                        cv[e] = cn;
                        hv[e] = rnd_tf32(og * tanhf(cn));
                    }
                    *(float2*)(Hout + (size_t)row * 256 + c0 + jj) = make_float2(hv[0], hv[1]);
                    *(float2*)(Cout + (size_t)row * 256 + c0 + jj) = make_float2(cv[0], cv[1]);
                }
            }
        }
    }
}

// ================= LEAF KERNEL — unchanged from R11 =================
#define BSTRL 136
#define LF_AF (128 * ASTR)          // 4608
#define LF_BF (32 * BSTRL)          // 4352
#define LF_STGF (LF_AF + LF_BF)     // 8960
#define LF_SMEM (2 * LF_STGF * 4)   // 71680

__global__ __launch_bounds__(256, 2) void leaf_fused(const int* __restrict__ ids,
                                                     const float* __restrict__ emb,
                                                     const float* __restrict__ bp,
                                                     float* __restrict__ Hout,
                                                     float* __restrict__ Cout) {
    extern __shared__ float dsm[];
    __shared__ int s_ids[128];
    __shared__ float s_bp[128];
    const int tid = threadIdx.x, wid = tid >> 5, lane = tid & 31;
    const int qr = lane >> 2, qc = lane & 3;
    const int wm = wid >> 1, wn = wid & 1;
    const int mBase = blockIdx.x * 128;
    const int nBase = blockIdx.y * 128;

    if (tid < 128) {
        s_ids[tid] = ids[mBase + tid];
        s_bp[tid] = bp[nBase + tid];
    }
    __syncthreads();

    float acc[2][8][4];
#pragma unroll
    for (int a = 0; a < 2; a++)
#pragma unroll
        for (int b = 0; b < 8; b++)
#pragma unroll
            for (int e = 0; e < 4; e++) acc[a][b][e] = 0.f;

    auto load_chunk = [&](int kc) {
        float* As = dsm + (kc & 1) * LF_STGF;
        float* Bs = As + LF_AF;
#pragma unroll
        for (int t = 0; t < 4; t++) {
            int v = tid + t * 256;
            int r = v >> 3, c = v & 7;
            cp16(As + r * ASTR + c * 4, emb + (size_t)s_ids[r] * 256 + kc * 32 + c * 4);
        }
#pragma unroll
        for (int t = 0; t < 4; t++) {
            int v = tid + t * 256;
            int kr = v >> 5, c4 = v & 31;
            cp16(Bs + kr * BSTRL + c4 * 4, g_WpK + (size_t)(kc * 32 + kr) * 256 + nBase + c4 * 4);
        }
        CP_COMMIT();
    };

    load_chunk(0);
    for (int i = 0; i < 8; i++) {
        if (i + 1 < 8) { load_chunk(i + 1); CP_WAIT1(); } else { CP_WAIT0(); }
        __syncthreads();
        const float* As = dsm + (i & 1) * LF_STGF;
        const float* Bs = As + LF_AF;
#pragma unroll
        for (int ks = 0; ks < 4; ks++) {
            uint32_t a[2][4];
#pragma unroll
            for (int ma = 0; ma < 2; ma++) {
                const float* ap = As + (wm * 32 + ma * 16 + qr) * ASTR + ks * 8 + qc;
                a[ma][0] = __float_as_uint(rnd_tf32(ap[0]));
                a[ma][1] = __float_as_uint(rnd_tf32(ap[8 * ASTR]));
                a[ma][2] = __float_as_uint(rnd_tf32(ap[4]));
                a[ma][3] = __float_as_uint(rnd_tf32(ap[8 * ASTR + 4]));
            }
            const float* brow = Bs + (ks * 8 + qc) * BSTRL;
#pragma unroll
            for (int na = 0; na < 8; na++) {
                int col = wn * 64 + na * 8 + qr;
                uint32_t b0 = __float_as_uint(brow[col]);
                uint32_t b1 = __float_as_uint(brow[4 * BSTRL + col]);
                mma_tf32(acc[0][na], a[0], b0, b1);
                mma_tf32(acc[1][na], a[1], b0, b1);
            }
        }
        __syncthreads();
    }

#pragma unroll
    for (int ma = 0; ma < 2; ma++) {
#pragma unroll
        for (int eh = 0; eh < 2; eh++) {
            int row = mBase + wm * 32 + ma * 16 + qr + eh * 8;
#pragma unroll
            for (int na = 0; na < 8; na++) {
                int cl = wn * 64 + na * 8 + qc * 2;
                float h0 = acc[ma][na][eh * 2 + 0] + s_bp[cl + 0];
                float h1 = acc[ma][na][eh * 2 + 1] + s_bp[cl + 1];
                *(float2*)(Hout + (size_t)row * 256 + nBase + cl) =
                    make_float2(rnd_tf32(h0), rnd_tf32(h1));
                *(float2*)(Cout + (size_t)row * 256 + nBase + cl) =
                    make_float2(tanhf(h0), tanhf(h1));
            }
        }
    }
}

// ================= PERSISTENT SMALL-LEVELS KERNEL — K-chunk=64 (8 chunks) =================
#define SL_GRID 128
#define ASTR64 68
#define SL_AF (64 * ASTR64)          // 4352 (64 rows x 64k + pad)
#define SL_BIMG 5248                 // one kc image slice (16 r x 160 p x 2, stride 328)
#define SL_BF (2 * SL_BIMG)          // 10496
#define SL_STGF (SL_AF + SL_BF)      // 14848
#define SL_SMEM (2 * SL_STGF * 4)    // 118784

__global__ __launch_bounds__(256, 1) void small_levels(float* __restrict__ inH0,
                                                       float* __restrict__ inC0,
                                                       float* __restrict__ outH0,
                                                       float* __restrict__ outC0,
                                                       const float* __restrict__ Wcls,
                                                       const float* __restrict__ bcls,
                                                       float* __restrict__ out) {
    extern __shared__ float dsm[];
    __shared__ float s_bias[160];
    const int tid = threadIdx.x, wid = tid >> 5, lane = tid & 31;
    const int qr = lane >> 2, qc = lane & 3;
    const int wm = wid >> 1, wn = wid & 1;

    unsigned gen = 0;
    if (tid == 0) gen = *(volatile unsigned*)&g_bar_gen;

    float* inH = inH0;  float* inC = inC0;
    float* outH = outH0; float* outC = outC0;

    int cur = 4096;
    while (cur > 16) {
        const int Mout = cur >> 1;
        const int mtiles = (Mout + 63) >> 6;
        const int nt = mtiles * 8;
        for (int t = blockIdx.x; t < nt; t += SL_GRID) {
            const int grp = t / mtiles;
            const int mtile = t - grp * mtiles;
            const int p0 = grp * 160, c0 = grp * 32;
            const int mBase = mtile * 64;

            for (int i = tid; i < 160; i += 256) s_bias[i] = g_bt[p0 + i];

            float acc[10][4];
#pragma unroll
            for (int b = 0; b < 10; b++)
#pragma unroll
                for (int e = 0; e < 4; e++) acc[b][e] = 0.f;

            // chunk cc covers k = cc*64 .. cc*64+63 (two kc images: 2cc, 2cc+1)
            auto load_chunk = [&](int cc) {
                float* As = dsm + (cc & 1) * SL_STGF;
                float* Bs = As + SL_AF;
#pragma unroll
                for (int tt = 0; tt < 4; tt++) {
                    int v = tid + tt * 256;             // 0..1023
                    int r = v >> 4, c = v & 15;          // r 0..63, c 0..15 (16B segs)
                    int row = mBase + r; if (row >= Mout) row = Mout - 1;
                    cp16(As + r * ASTR64 + c * 4, inH + (size_t)row * 512 + cc * 64 + c * 4);
                }
#pragma unroll
                for (int tt = 0; tt < 10; tt++) {
                    int v = tid + tt * 256;              // 0..2559
                    int img = v / 1280, w = v - img * 1280;
                    int kr = w / 80, c4 = w - kr * 80;
                    cp16(Bs + img * SL_BIMG + kr * BSTR2 + c4 * 4,
                         g_Wk + (size_t)((2 * cc + img) * 16 + kr) * 2560 + p0 * 2 + c4 * 4);
                }
                CP_COMMIT();
            };

            load_chunk(0);
            for (int i = 0; i < 8; i++) {
                if (i + 1 < 8) { load_chunk(i + 1); CP_WAIT1(); } else { CP_WAIT0(); }
                __syncthreads();
                const float* As = dsm + (i & 1) * SL_STGF;
                const float* Bs = As + SL_AF;
#pragma unroll
                for (int ks = 0; ks < 8; ks++) {
                    uint32_t a[4];
                    const float* ap = As + (wm * 16 + qr) * ASTR64 + ks * 8 + qc;
                    a[0] = __float_as_uint(ap[0]);
                    a[1] = __float_as_uint(ap[8 * ASTR64]);
                    a[2] = __float_as_uint(ap[4]);
                    a[3] = __float_as_uint(ap[8 * ASTR64 + 4]);
                    const float* brow = Bs + (ks >> 2) * SL_BIMG + ((ks & 3) * 4 + qc) * BSTR2;
#pragma unroll
                    for (int na = 0; na < 10; na++) {
                        int col = (na >> 1) * 32 + wn * 16 + (na & 1) * 8 + qr;
                        float2 bf = *(const float2*)(brow + col * 2);
                        mma_tf32(acc[na], a, __float_as_uint(bf.x), __float_as_uint(bf.y));
                    }
                }
                __syncthreads();
            }

#pragma unroll
            for (int eh = 0; eh < 2; eh++) {
                int row = mBase + wm * 16 + qr + eh * 8;
                if (row < Mout) {
#pragma unroll
                    for (int na = 0; na < 2; na++) {
                        int jj = wn * 16 + na * 8 + qc * 2;
                        float2 cl = *(const float2*)(inC + (size_t)row * 512 + c0 + jj);
                        float2 cr = *(const float2*)(inC + (size_t)row * 512 + 256 + c0 + jj);
                        float hv[2], cv[2];
#pragma unroll
                        for (int e = 0; e < 2; e++) {
                            int bi_ = jj + e;
                            float fl = sigm(acc[0 * 2 + na][eh * 2 + e] + s_bias[0 * 32 + bi_]);
                            float fr = sigm(acc[1 * 2 + na][eh * 2 + e] + s_bias[1 * 32 + bi_]);
                            float ig = sigm(acc[2 * 2 + na][eh * 2 + e] + s_bias[2 * 32 + bi_]);
                            float og = sigm(acc[3 * 2 + na][eh * 2 + e] + s_bias[3 * 32 + bi_]);
                            float cc2 = tanhf(acc[4 * 2 + na][eh * 2 + e] + s_bias[4 * 32 + bi_]);
                            float clv = (e == 0) ? cl.x : cl.y;
                            float crv = (e == 0) ? cr.x : cr.y;
                            float cn = fl * clv + fr * crv + ig * cc2;
                            cv[e] = cn;
                            hv[e] = rnd_tf32(og * tanhf(cn));
                        }
                        *(float2*)(outH + (size_t)row * 256 + c0 + jj) = make_float2(hv[0], hv[1]);
                        *(float2*)(outC + (size_t)row * 256 + c0 + jj) = make_float2(cv[0], cv[1]);
                    }
                }
            }
            __syncthreads();
        }

        // -------- grid-wide barrier --------
        __threadfence();
        __syncthreads();
        if (tid == 0) {
            unsigned arrived = atomicAdd(&g_bar_cnt, 1u);
            if (arrived == SL_GRID - 1) {
                g_bar_cnt = 0;
                __threadfence();
                atomicAdd(&g_bar_gen, 1u);
                gen++;
            } else {
                unsigned cg;
                do {
                    __nanosleep(64);
                    asm volatile("ld.acquire.gpu.u32 %0, [%1];" : "=r"(cg) : "l"(&g_bar_gen) : "memory");
                } while (cg == gen);
                gen = cg;
                __threadfence();
            }
        }
        __syncthreads();

        float* th = inH; inH = outH; outH = th;
        float* tc = inC; inC = outC; outC = tc;
        cur = Mout;
    }

    // classifier on root H — CTA 0
    if (blockIdx.x == 0 && tid < BVAL * 2) {
        int b = tid >> 1, cx = tid & 1;
        float sum = bcls[cx];
        const float* h = inH + (size_t)b * HVAL;
        for (int k = 0; k < HVAL; k++) sum += h[k] * Wcls[k * 2 + cx];
        out[b * 2 + cx] = sum;
    }
}

// ---------------- launch ----------------
extern "C" void kernel_launch(void* const* d_in, const int* in_sizes, int n_in,
                              void* d_out, int out_size) {
    const int*   leaf_ids = (const int*)d_in[0];
    const float* emb  = (const float*)d_in[1];
    const float* Wp   = (const float*)d_in[2];
    const float* bp   = (const float*)d_in[3];
    const float* Wfl  = (const float*)d_in[4];
    const float* bfl  = (const float*)d_in[5];
    const float* Wfr  = (const float*)d_in[6];
    const float* bfr  = (const float*)d_in[7];
    const float* Wi   = (const float*)d_in[8];
    const float* bi   = (const float*)d_in[9];
    const float* Wo   = (const float*)d_in[10];
    const float* bo   = (const float*)d_in[11];
    const float* Wc   = (const float*)d_in[12];
    const float* bc   = (const float*)d_in[13];
    const float* Wcls = (const float*)d_in[14];
    const float* bcls = (const float*)d_in[15];
    float* out = (float*)d_out;

    float *Ah, *Ac, *Bh, *Bc;
    cudaGetSymbolAddress((void**)&Ah, g_bufA_h);
    cudaGetSymbolAddress((void**)&Ac, g_bufA_c);
    cudaGetSymbolAddress((void**)&Bh, g_bufB_h);
    cudaGetSymbolAddress((void**)&Bc, g_bufB_c);

    cudaFuncSetAttribute(level_fused,  cudaFuncAttributeMaxDynamicSharedMemorySize, LV_SMEM);
    cudaFuncSetAttribute(leaf_fused,   cudaFuncAttributeMaxDynamicSharedMemorySize, LF_SMEM);
    cudaFuncSetAttribute(small_levels, cudaFuncAttributeMaxDynamicSharedMemorySize, SL_SMEM);

    pack_weights<<<256, 256>>>(Wp, Wfl, Wfr, Wi, Wo, Wc, bfl, bfr, bi, bo, bc);

    leaf_fused<<<dim3(NODES0 / 128, 2), 256, LF_SMEM>>>(leaf_ids, emb, bp, Ah, Ac);

    float *inH = Ah, *inC = Ac, *outH = Bh, *outC = Bc;
    int cur = NODES0;
    while (cur > 4096) {
        int Mout = cur >> 1;
        dim3 grid(Mout / 128, 8);
        level_fused<<<grid, 256, LV_SMEM>>>(inH, inC, outH, outC, Mout);
        float* t;
        t = inH; inH = outH; outH = t;
        t = inC; inC = outC; outC = t;
        cur = Mout;
    }

    small_levels<<<SL_GRID, 256, SL_SMEM>>>(inH, inC, outH, outC, Wcls, bcls, out);
}

// round 13
// speedup vs baseline: 1.4655x; 1.4655x over previous
#include <cuda_runtime.h>
#include <cstdint>
#include <math.h>

#define BVAL 16
#define HVAL 256
#define NODES0 65536

// ---------------- device scratch ----------------
__device__ __align__(16) float g_bufA_h[(size_t)NODES0 * HVAL];
__device__ __align__(16) float g_bufA_c[(size_t)NODES0 * HVAL];
__device__ __align__(16) float g_bufB_h[(size_t)(NODES0 / 2) * HVAL];
__device__ __align__(16) float g_bufB_c[(size_t)(NODES0 / 2) * HVAL];
// g_Wk chunk images: [kc(16)][r(16)=ks*4+qc][p(1280)][pair(2)]; pair=(k, k+4), k=kc*32+ks*8+qc
__device__ __align__(16) float g_Wk[(size_t)16 * 16 * 1280 * 2];
// g_WpK flat [k(256)][n(256)], tf32-RN
__device__ __align__(16) float g_WpK[(size_t)256 * 256];
__device__ __align__(16) float g_bt[1280];                  // packed gate biases

__device__ unsigned g_bar_cnt = 0;
__device__ unsigned g_bar_gen = 0;

// ---------------- helpers ----------------
__device__ __forceinline__ float rnd_tf32(float x) {
    uint32_t r;
    asm("cvt.rna.tf32.f32 %0, %1;" : "=r"(r) : "f"(x));
    return __uint_as_float(r);
}
__device__ __forceinline__ float sigm(float x) { return 1.0f / (1.0f + __expf(-x)); }

__device__ __forceinline__ void cp16(void* dst, const float* src) {
    uint32_t d = (uint32_t)__cvta_generic_to_shared(dst);
    asm volatile("cp.async.cg.shared.global [%0], [%1], 16;"
                 :: "r"(d), "l"(__cvta_generic_to_global(src)));
}
#define CP_COMMIT() asm volatile("cp.async.commit_group;" ::: "memory")
#define CP_WAIT1()  asm volatile("cp.async.wait_group 1;" ::: "memory")
#define CP_WAIT0()  asm volatile("cp.async.wait_group 0;" ::: "memory")

__device__ __forceinline__ void mma_tf32(float* c, const uint32_t* a, uint32_t b0, uint32_t b1) {
    asm volatile("mma.sync.aligned.m16n8k8.row.col.f32.tf32.tf32.f32 "
                 "{%0,%1,%2,%3}, {%4,%5,%6,%7}, {%8,%9}, {%0,%1,%2,%3};"
                 : "+f"(c[0]), "+f"(c[1]), "+f"(c[2]), "+f"(c[3])
                 : "r"(a[0]), "r"(a[1]), "r"(a[2]), "r"(a[3]), "r"(b0), "r"(b1));
}

// ---------------- pack kernel (weights only) ----------------
__global__ void pack_weights(const float* __restrict__ Wp,
                             const float* __restrict__ Wfl, const float* __restrict__ Wfr,
                             const float* __restrict__ Wi,  const float* __restrict__ Wo,
                             const float* __restrict__ Wc,
                             const float* __restrict__ bfl, const float* __restrict__ bfr,
                             const float* __restrict__ bi,  const float* __restrict__ bo,
                             const float* __restrict__ bc) {
    int idx = blockIdx.x * blockDim.x + threadIdx.x;
    int stride = gridDim.x * blockDim.x;
    for (int i = idx; i < 16 * 16 * 1280 * 2; i += stride) {
        int e = i & 1;
        int t = i >> 1;
        int p = t % 1280;
        int rr = t / 1280;
        int r = rr & 15, kc = rr >> 4;
        int k = kc * 32 + (r >> 2) * 8 + (r & 3) + e * 4;
        int grp = p / 160, rem = p - grp * 160;
        int g5 = rem >> 5, jj = rem & 31;
        const float* W = (g5 == 0) ? Wfl : (g5 == 1) ? Wfr : (g5 == 2) ? Wi : (g5 == 3) ? Wo : Wc;
        g_Wk[i] = rnd_tf32(W[k * 256 + grp * 32 + jj]);
    }
    for (int i = idx; i < 256 * 256; i += stride) g_WpK[i] = rnd_tf32(Wp[i]);
    for (int i = idx; i < 1280; i += stride) {
        int grp = i / 160, rem = i - grp * 160;
        int g5 = rem >> 5, jj = rem & 31;
        const float* bb = (g5 == 0) ? bfl : (g5 == 1) ? bfr : (g5 == 2) ? bi : (g5 == 3) ? bo : bc;
        g_bt[i] = bb[grp * 32 + jj];
    }
}

// ================= LEVEL KERNEL (all launched levels) — R11 verbatim =================
#define ASTR 36
#define BSTR2 328
#define LV_AF (128 * ASTR)          // 4608
#define LV_BF (16 * BSTR2)          // 5248
#define LV_STGF (LV_AF + LV_BF)     // 9856
#define LV_SMEM (2 * LV_STGF * 4)   // 78848

__global__ __launch_bounds__(256, 2) void level_fused(const float* __restrict__ Hin,
                                                      const float* __restrict__ Cin,
                                                      float* __restrict__ Hout,
                                                      float* __restrict__ Cout, int Mout) {
    extern __shared__ float dsm[];
    __shared__ float s_bias[160];
    const int tid = threadIdx.x, wid = tid >> 5, lane = tid & 31;
    const int qr = lane >> 2, qc = lane & 3;
    const int wm = wid >> 1, wn = wid & 1;
    const int mBase = blockIdx.x * 128;
    const int grp = blockIdx.y;
    const int p0 = grp * 160, c0 = grp * 32;

    for (int i = tid; i < 160; i += 256) s_bias[i] = g_bt[p0 + i];

    float acc[2][10][4];
#pragma unroll
    for (int a = 0; a < 2; a++)
#pragma unroll
        for (int b = 0; b < 10; b++)
#pragma unroll
            for (int e = 0; e < 4; e++) acc[a][b][e] = 0.f;

    auto load_chunk = [&](int kc) {
        float* As = dsm + (kc & 1) * LV_STGF;
        float* Bs = As + LV_AF;
#pragma unroll
        for (int t = 0; t < 4; t++) {
            int v = tid + t * 256;
            int r = v >> 3, c = v & 7;
            int row = mBase + r; if (row >= Mout) row = Mout - 1;
            cp16(As + r * ASTR + c * 4, Hin + (size_t)row * 512 + kc * 32 + c * 4);
        }
#pragma unroll
        for (int t = 0; t < 5; t++) {
            int v = tid + t * 256;
            int kr = v / 80, c4 = v - kr * 80;
            cp16(Bs + kr * BSTR2 + c4 * 4,
                 g_Wk + (size_t)(kc * 16 + kr) * 2560 + p0 * 2 + c4 * 4);
        }
        CP_COMMIT();
    };

    load_chunk(0);
    for (int i = 0; i < 16; i++) {
        if (i + 1 < 16) { load_chunk(i + 1); CP_WAIT1(); } else { CP_WAIT0(); }
        __syncthreads();
        const float* As = dsm + (i & 1) * LV_STGF;
        const float* Bs = As + LV_AF;
#pragma unroll
        for (int ks = 0; ks < 4; ks++) {
            uint32_t a[2][4];
#pragma unroll
            for (int ma = 0; ma < 2; ma++) {
                const float* ap = As + (wm * 32 + ma * 16 + qr) * ASTR + ks * 8 + qc;
                a[ma][0] = __float_as_uint(ap[0]);
                a[ma][1] = __float_as_uint(ap[8 * ASTR]);
                a[ma][2] = __float_as_uint(ap[4]);
                a[ma][3] = __float_as_uint(ap[8 * ASTR + 4]);
            }
            const float* brow = Bs + (ks * 4 + qc) * BSTR2;
#pragma unroll
            for (int na = 0; na < 10; na++) {
                int col = (na >> 1) * 32 + wn * 16 + (na & 1) * 8 + qr;
                float2 bf = *(const float2*)(brow + col * 2);
                uint32_t b0 = __float_as_uint(bf.x);
                uint32_t b1 = __float_as_uint(bf.y);
                mma_tf32(acc[0][na], a[0], b0, b1);
                mma_tf32(acc[1][na], a[1], b0, b1);
            }
        }
        __syncthreads();
    }

#pragma unroll
    for (int ma = 0; ma < 2; ma++) {
#pragma unroll
        for (int eh = 0; eh < 2; eh++) {
            int row = mBase + wm * 32 + ma * 16 + qr + eh * 8;
            if (row < Mout) {
#pragma unroll
                for (int na = 0; na < 2; na++) {
                    int jj = wn * 16 + na * 8 + qc * 2;
                    float2 cl = *(const float2*)(Cin + (size_t)row * 512 + c0 + jj);
                    float2 cr = *(const float2*)(Cin + (size_t)row * 512 + 256 + c0 + jj);
                    float hv[2], cv[2];
#pragma unroll
                    for (int e = 0; e < 2; e++) {
                        int bi_ = jj + e;
                        float fl = sigm(acc[ma][0 * 2 + na][eh * 2 + e] + s_bias[0 * 32 + bi_]);
                        float fr = sigm(acc[ma][1 * 2 + na][eh * 2 + e] + s_bias[1 * 32 + bi_]);
                        float ig = sigm(acc[ma][2 * 2 + na][eh * 2 + e] + s_bias[2 * 32 + bi_]);
                        float og = sigm(acc[ma][3 * 2 + na][eh * 2 + e] + s_bias[3 * 32 + bi_]);
                        float cc = tanhf(acc[ma][4 * 2 + na][eh * 2 + e] + s_bias[4 * 32 + bi_]);
                        float clv = (e == 0) ? cl.x : cl.y;
                        float crv = (e == 0) ? cr.x : cr.y;
                        float cn = fl * clv + fr * crv + ig * cc;
                        cv[e] = cn;
                        hv[e] = rnd_tf32(og * tanhf(cn));
                    }
                    *(float2*)(Hout + (size_t)row * 256 + c0 + jj) = make_float2(hv[0], hv[1]);
                    *(float2*)(Cout + (size_t)row * 256 + c0 + jj) = make_float2(cv[0], cv[1]);
                }
            }
        }
    }
}

// ================= LEAF KERNEL — R11 verbatim =================
#define BSTRL 136
#define LF_AF (128 * ASTR)          // 4608
#define LF_BF (32 * BSTRL)          // 4352
#define LF_STGF (LF_AF + LF_BF)     // 8960
#define LF_SMEM (2 * LF_STGF * 4)   // 71680

__global__ __launch_bounds__(256, 2) void leaf_fused(const int* __restrict__ ids,
                                                     const float* __restrict__ emb,
                                                     const float* __restrict__ bp,
                                                     float* __restrict__ Hout,
                                                     float* __restrict__ Cout) {
    extern __shared__ float dsm[];
    __shared__ int s_ids[128];
    __shared__ float s_bp[128];
    const int tid = threadIdx.x, wid = tid >> 5, lane = tid & 31;
    const int qr = lane >> 2, qc = lane & 3;
    const int wm = wid >> 1, wn = wid & 1;
    const int mBase = blockIdx.x * 128;
    const int nBase = blockIdx.y * 128;

    if (tid < 128) {
        s_ids[tid] = ids[mBase + tid];
        s_bp[tid] = bp[nBase + tid];
    }
    __syncthreads();

    float acc[2][8][4];
#pragma unroll
    for (int a = 0; a < 2; a++)
#pragma unroll
        for (int b = 0; b < 8; b++)
#pragma unroll
            for (int e = 0; e < 4; e++) acc[a][b][e] = 0.f;

    auto load_chunk = [&](int kc) {
        float* As = dsm + (kc & 1) * LF_STGF;
        float* Bs = As + LF_AF;
#pragma unroll
        for (int t = 0; t < 4; t++) {
            int v = tid + t * 256;
            int r = v >> 3, c = v & 7;
            cp16(As + r * ASTR + c * 4, emb + (size_t)s_ids[r] * 256 + kc * 32 + c * 4);
        }
#pragma unroll
        for (int t = 0; t < 4; t++) {
            int v = tid + t * 256;
            int kr = v >> 5, c4 = v & 31;
            cp16(Bs + kr * BSTRL + c4 * 4, g_WpK + (size_t)(kc * 32 + kr) * 256 + nBase + c4 * 4);
        }
        CP_COMMIT();
    };

    load_chunk(0);
    for (int i = 0; i < 8; i++) {
        if (i + 1 < 8) { load_chunk(i + 1); CP_WAIT1(); } else { CP_WAIT0(); }
        __syncthreads();
        const float* As = dsm + (i & 1) * LF_STGF;
        const float* Bs = As + LF_AF;
#pragma unroll
        for (int ks = 0; ks < 4; ks++) {
            uint32_t a[2][4];
#pragma unroll
            for (int ma = 0; ma < 2; ma++) {
                const float* ap = As + (wm * 32 + ma * 16 + qr) * ASTR + ks * 8 + qc;
                a[ma][0] = __float_as_uint(rnd_tf32(ap[0]));
                a[ma][1] = __float_as_uint(rnd_tf32(ap[8 * ASTR]));
                a[ma][2] = __float_as_uint(rnd_tf32(ap[4]));
                a[ma][3] = __float_as_uint(rnd_tf32(ap[8 * ASTR + 4]));
            }
            const float* brow = Bs + (ks * 8 + qc) * BSTRL;
#pragma unroll
            for (int na = 0; na < 8; na++) {
                int col = wn * 64 + na * 8 + qr;
                uint32_t b0 = __float_as_uint(brow[col]);
                uint32_t b1 = __float_as_uint(brow[4 * BSTRL + col]);
                mma_tf32(acc[0][na], a[0], b0, b1);
                mma_tf32(acc[1][na], a[1], b0, b1);
            }
        }
        __syncthreads();
    }

#pragma unroll
    for (int ma = 0; ma < 2; ma++) {
#pragma unroll
        for (int eh = 0; eh < 2; eh++) {
            int row = mBase + wm * 32 + ma * 16 + qr + eh * 8;
#pragma unroll
            for (int na = 0; na < 8; na++) {
                int cl = wn * 64 + na * 8 + qc * 2;
                float h0 = acc[ma][na][eh * 2 + 0] + s_bp[cl + 0];
                float h1 = acc[ma][na][eh * 2 + 1] + s_bp[cl + 1];
                *(float2*)(Hout + (size_t)row * 256 + nBase + cl) =
                    make_float2(rnd_tf32(h0), rnd_tf32(h1));
                *(float2*)(Cout + (size_t)row * 256 + nBase + cl) =
                    make_float2(tanhf(h0), tanhf(h1));
            }
        }
    }
}

// ================= PERSISTENT SMALL-LEVELS KERNEL — R11 verbatim, last 4 levels only =================
#define SL_GRID 128
#define SL_AF (64 * ASTR)           // 2304
#define SL_BF (16 * BSTR2)          // 5248
#define SL_STGF (SL_AF + SL_BF)     // 7552
#define SL_SMEM (2 * SL_STGF * 4)   // 60416

__global__ __launch_bounds__(256, 1) void small_levels(float* __restrict__ inH0,
                                                       float* __restrict__ inC0,
                                                       float* __restrict__ outH0,
                                                       float* __restrict__ outC0,
                                                       const float* __restrict__ Wcls,
                                                       const float* __restrict__ bcls,
                                                       float* __restrict__ out) {
    extern __shared__ float dsm[];
    __shared__ float s_bias[160];
    const int tid = threadIdx.x, wid = tid >> 5, lane = tid & 31;
    const int qr = lane >> 2, qc = lane & 3;
    const int wm = wid >> 1, wn = wid & 1;

    unsigned gen = 0;
    if (tid == 0) gen = *(volatile unsigned*)&g_bar_gen;

    float* inH = inH0;  float* inC = inC0;
    float* outH = outH0; float* outC = outC0;

    int cur = 256;                      // launched levels handled cur down to 256
    while (cur > 16) {
        const int Mout = cur >> 1;
        const int mtiles = (Mout + 63) >> 6;
        const int nt = mtiles * 8;
        for (int t = blockIdx.x; t < nt; t += SL_GRID) {
            const int grp = t / mtiles;
            const int mtile = t - grp * mtiles;
            const int p0 = grp * 160, c0 = grp * 32;
            const int mBase = mtile * 64;

            for (int i = tid; i < 160; i += 256) s_bias[i] = g_bt[p0 + i];

            float acc[10][4];
#pragma unroll
            for (int b = 0; b < 10; b++)
#pragma unroll
                for (int e = 0; e < 4; e++) acc[b][e] = 0.f;

            auto load_chunk = [&](int kc) {
                float* As = dsm + (kc & 1) * SL_STGF;
                float* Bs = As + SL_AF;
#pragma unroll
                for (int tt = 0; tt < 2; tt++) {
                    int v = tid + tt * 256;
                    int r = v >> 3, c = v & 7;
                    int row = mBase + r; if (row >= Mout) row = Mout - 1;
                    cp16(As + r * ASTR + c * 4, inH + (size_t)row * 512 + kc * 32 + c * 4);
                }
#pragma unroll
                for (int tt = 0; tt < 5; tt++) {
                    int v = tid + tt * 256;
                    int kr = v / 80, c4 = v - kr * 80;
                    cp16(Bs + kr * BSTR2 + c4 * 4,
                         g_Wk + (size_t)(kc * 16 + kr) * 2560 + p0 * 2 + c4 * 4);
                }
                CP_COMMIT();
            };

            load_chunk(0);
            for (int i = 0; i < 16; i++) {
                if (i + 1 < 16) { load_chunk(i + 1); CP_WAIT1(); } else { CP_WAIT0(); }
                __syncthreads();
                const float* As = dsm + (i & 1) * SL_STGF;
                const float* Bs = As + SL_AF;
#pragma unroll
                for (int ks = 0; ks < 4; ks++) {
                    uint32_t a[4];
                    const float* ap = As + (wm * 16 + qr) * ASTR + ks * 8 + qc;
                    a[0] = __float_as_uint(ap[0]);
                    a[1] = __float_as_uint(ap[8 * ASTR]);
                    a[2] = __float_as_uint(ap[4]);
                    a[3] = __float_as_uint(ap[8 * ASTR + 4]);
                    const float* brow = Bs + (ks * 4 + qc) * BSTR2;
#pragma unroll
                    for (int na = 0; na < 10; na++) {
                        int col = (na >> 1) * 32 + wn * 16 + (na & 1) * 8 + qr;
                        float2 bf = *(const float2*)(brow + col * 2);
                        mma_tf32(acc[na], a, __float_as_uint(bf.x), __float_as_uint(bf.y));
                    }
                }
                __syncthreads();
            }

#pragma unroll
            for (int eh = 0; eh < 2; eh++) {
                int row = mBase + wm * 16 + qr + eh * 8;
                if (row < Mout) {
#pragma unroll
                    for (int na = 0; na < 2; na++) {
                        int jj = wn * 16 + na * 8 + qc * 2;
                        float2 cl = *(const float2*)(inC + (size_t)row * 512 + c0 + jj);
                        float2 cr = *(const float2*)(inC + (size_t)row * 512 + 256 + c0 + jj);
                        float hv[2], cv[2];
#pragma unroll
                        for (int e = 0; e < 2; e++) {
                            int bi_ = jj + e;
                            float fl = sigm(acc[0 * 2 + na][eh * 2 + e] + s_bias[0 * 32 + bi_]);
                            float fr = sigm(acc[1 * 2 + na][eh * 2 + e] + s_bias[1 * 32 + bi_]);
                            float ig = sigm(acc[2 * 2 + na][eh * 2 + e] + s_bias[2 * 32 + bi_]);
                            float og = sigm(acc[3 * 2 + na][eh * 2 + e] + s_bias[3 * 32 + bi_]);
                            float cc = tanhf(acc[4 * 2 + na][eh * 2 + e] + s_bias[4 * 32 + bi_]);
                            float clv = (e == 0) ? cl.x : cl.y;
                            float crv = (e == 0) ? cr.x : cr.y;
                            float cn = fl * clv + fr * crv + ig * cc;
                            cv[e] = cn;
                            hv[e] = rnd_tf32(og * tanhf(cn));
                        }
                        *(float2*)(outH + (size_t)row * 256 + c0 + jj) = make_float2(hv[0], hv[1]);
                        *(float2*)(outC + (size_t)row * 256 + c0 + jj) = make_float2(cv[0], cv[1]);
                    }
                }
            }
            __syncthreads();
        }

        // -------- grid-wide barrier --------
        __threadfence();
        __syncthreads();
        if (tid == 0) {
            unsigned arrived = atomicAdd(&g_bar_cnt, 1u);
            if (arrived == SL_GRID - 1) {
                g_bar_cnt = 0;
                __threadfence();
                atomicAdd(&g_bar_gen, 1u);
                gen++;
            } else {
                unsigned cg;
                do {
                    __nanosleep(64);
                    asm volatile("ld.acquire.gpu.u32 %0, [%1];" : "=r"(cg) : "l"(&g_bar_gen) : "memory");
                } while (cg == gen);
                gen = cg;
                __threadfence();
            }
        }
        __syncthreads();

        float* th = inH; inH = outH; outH = th;
        float* tc = inC; inC = outC; outC = tc;
        cur = Mout;
    }

    // classifier on root H — CTA 0
    if (blockIdx.x == 0 && tid < BVAL * 2) {
        int b = tid >> 1, cx = tid & 1;
        float sum = bcls[cx];
        const float* h = inH + (size_t)b * HVAL;
        for (int k = 0; k < HVAL; k++) sum += h[k] * Wcls[k * 2 + cx];
        out[b * 2 + cx] = sum;
    }
}

// ---------------- launch ----------------
extern "C" void kernel_launch(void* const* d_in, const int* in_sizes, int n_in,
                              void* d_out, int out_size) {
    const int*   leaf_ids = (const int*)d_in[0];
    const float* emb  = (const float*)d_in[1];
    const float* Wp   = (const float*)d_in[2];
    const float* bp   = (const float*)d_in[3];
    const float* Wfl  = (const float*)d_in[4];
    const float* bfl  = (const float*)d_in[5];
    const float* Wfr  = (const float*)d_in[6];
    const float* bfr  = (const float*)d_in[7];
    const float* Wi   = (const float*)d_in[8];
    const float* bi   = (const float*)d_in[9];
    const float* Wo   = (const float*)d_in[10];
    const float* bo   = (const float*)d_in[11];
    const float* Wc   = (const float*)d_in[12];
    const float* bc   = (const float*)d_in[13];
    const float* Wcls = (const float*)d_in[14];
    const float* bcls = (const float*)d_in[15];
    float* out = (float*)d_out;

    float *Ah, *Ac, *Bh, *Bc;
    cudaGetSymbolAddress((void**)&Ah, g_bufA_h);
    cudaGetSymbolAddress((void**)&Ac, g_bufA_c);
    cudaGetSymbolAddress((void**)&Bh, g_bufB_h);
    cudaGetSymbolAddress((void**)&Bc, g_bufB_c);

    cudaFuncSetAttribute(level_fused,  cudaFuncAttributeMaxDynamicSharedMemorySize, LV_SMEM);
    cudaFuncSetAttribute(leaf_fused,   cudaFuncAttributeMaxDynamicSharedMemorySize, LF_SMEM);
    cudaFuncSetAttribute(small_levels, cudaFuncAttributeMaxDynamicSharedMemorySize, SL_SMEM);

    pack_weights<<<256, 256>>>(Wp, Wfl, Wfr, Wi, Wo, Wc, bfl, bfr, bi, bo, bc);

    leaf_fused<<<dim3(NODES0 / 128, 2), 256, LF_SMEM>>>(leaf_ids, emb, bp, Ah, Ac);

    float *inH = Ah, *inC = Ac, *outH = Bh, *outC = Bc;
    int cur = NODES0;
    while (cur > 256) {                  // launched levels down to Mout=256
        int Mout = cur >> 1;
        dim3 grid((Mout + 127) / 128, 8);
        level_fused<<<grid, 256, LV_SMEM>>>(inH, inC, outH, outC, Mout);
        float* t;
        t = inH; inH = outH; outH = t;
        t = inC; inC = outC; outC = t;
        cur = Mout;
    }

    // cur == 256; persistent kernel: last 4 levels + classifier
    small_levels<<<SL_GRID, 256, SL_SMEM>>>(inH, inC, outH, outC, Wcls, bcls, out);
}

// round 16
// speedup vs baseline: 1.4880x; 1.0154x over previous
#include <cuda_runtime.h>
#include <cstdint>
#include <math.h>

#define BVAL 16
#define HVAL 256
#define NODES0 65536

// ---------------- device scratch ----------------
__device__ __align__(16) float g_bufA_h[(size_t)NODES0 * HVAL];
__device__ __align__(16) float g_bufA_c[(size_t)NODES0 * HVAL];
__device__ __align__(16) float g_bufB_h[(size_t)(NODES0 / 2) * HVAL];
__device__ __align__(16) float g_bufB_c[(size_t)(NODES0 / 2) * HVAL];
// g_Wk chunk images: [kc(16)][r(16)=ks*4+qc][p(1280)][pair(2)]; pair=(k, k+4), k=kc*32+ks*8+qc
__device__ __align__(16) float g_Wk[(size_t)16 * 16 * 1280 * 2];
// g_WpK flat [k(256)][n(256)], tf32-RN
__device__ __align__(16) float g_WpK[(size_t)256 * 256];
__device__ __align__(16) float g_bt[1280];                  // packed gate biases

__device__ unsigned g_bar_cnt = 0;
__device__ unsigned g_bar_gen = 0;

// ---------------- helpers ----------------
__device__ __forceinline__ float rnd_tf32(float x) {
    uint32_t r;
    asm("cvt.rna.tf32.f32 %0, %1;" : "=r"(r) : "f"(x));
    return __uint_as_float(r);
}
__device__ __forceinline__ float sigm(float x) { return 1.0f / (1.0f + __expf(-x)); }

__device__ __forceinline__ void cp16(void* dst, const float* src) {
    uint32_t d = (uint32_t)__cvta_generic_to_shared(dst);
    asm volatile("cp.async.cg.shared.global [%0], [%1], 16;"
                 :: "r"(d), "l"(__cvta_generic_to_global(src)));
}
#define CP_COMMIT() asm volatile("cp.async.commit_group;" ::: "memory")
#define CP_WAIT2()  asm volatile("cp.async.wait_group 2;" ::: "memory")
#define CP_WAIT1()  asm volatile("cp.async.wait_group 1;" ::: "memory")
#define CP_WAIT0()  asm volatile("cp.async.wait_group 0;" ::: "memory")

__device__ __forceinline__ void mma_tf32(float* c, const uint32_t* a, uint32_t b0, uint32_t b1) {
    asm volatile("mma.sync.aligned.m16n8k8.row.col.f32.tf32.tf32.f32 "
                 "{%0,%1,%2,%3}, {%4,%5,%6,%7}, {%8,%9}, {%0,%1,%2,%3};"
                 : "+f"(c[0]), "+f"(c[1]), "+f"(c[2]), "+f"(c[3])
                 : "r"(a[0]), "r"(a[1]), "r"(a[2]), "r"(a[3]), "r"(b0), "r"(b1));
}

// ---------------- pack kernel (weights only) ----------------
__global__ void pack_weights(const float* __restrict__ Wp,
                             const float* __restrict__ Wfl, const float* __restrict__ Wfr,
                             const float* __restrict__ Wi,  const float* __restrict__ Wo,
                             const float* __restrict__ Wc,
                             const float* __restrict__ bfl, const float* __restrict__ bfr,
                             const float* __restrict__ bi,  const float* __restrict__ bo,
                             const float* __restrict__ bc) {
    int idx = blockIdx.x * blockDim.x + threadIdx.x;
    int stride = gridDim.x * blockDim.x;
    for (int i = idx; i < 16 * 16 * 1280 * 2; i += stride) {
        int e = i & 1;
        int t = i >> 1;
        int p = t % 1280;
        int rr = t / 1280;
        int r = rr & 15, kc = rr >> 4;
        int k = kc * 32 + (r >> 2) * 8 + (r & 3) + e * 4;
        int grp = p / 160, rem = p - grp * 160;
        int g5 = rem >> 5, jj = rem & 31;
        const float* W = (g5 == 0) ? Wfl : (g5 == 1) ? Wfr : (g5 == 2) ? Wi : (g5 == 3) ? Wo : Wc;
        g_Wk[i] = rnd_tf32(W[k * 256 + grp * 32 + jj]);
    }
    for (int i = idx; i < 256 * 256; i += stride) g_WpK[i] = rnd_tf32(Wp[i]);
    for (int i = idx; i < 1280; i += stride) {
        int grp = i / 160, rem = i - grp * 160;
        int g5 = rem >> 5, jj = rem & 31;
        const float* bb = (g5 == 0) ? bfl : (g5 == 1) ? bfr : (g5 == 2) ? bi : (g5 == 3) ? bo : bc;
        g_bt[i] = bb[grp * 32 + jj];
    }
}

// ================= LEVEL KERNEL (big levels) — R11 verbatim =================
#define ASTR 36
#define BSTR2 328
#define LV_AF (128 * ASTR)          // 4608
#define LV_BF (16 * BSTR2)          // 5248
#define LV_STGF (LV_AF + LV_BF)     // 9856
#define LV_SMEM (2 * LV_STGF * 4)   // 78848

__global__ __launch_bounds__(256, 2) void level_fused(const float* __restrict__ Hin,
                                                      const float* __restrict__ Cin,
                                                      float* __restrict__ Hout,
                                                      float* __restrict__ Cout, int Mout) {
    extern __shared__ float dsm[];
    __shared__ float s_bias[160];
    const int tid = threadIdx.x, wid = tid >> 5, lane = tid & 31;
    const int qr = lane >> 2, qc = lane & 3;
    const int wm = wid >> 1, wn = wid & 1;
    const int mBase = blockIdx.x * 128;
    const int grp = blockIdx.y;
    const int p0 = grp * 160, c0 = grp * 32;

    for (int i = tid; i < 160; i += 256) s_bias[i] = g_bt[p0 + i];

    float acc[2][10][4];
#pragma unroll
    for (int a = 0; a < 2; a++)
#pragma unroll
        for (int b = 0; b < 10; b++)
#pragma unroll
            for (int e = 0; e < 4; e++) acc[a][b][e] = 0.f;

    auto load_chunk = [&](int kc) {
        float* As = dsm + (kc & 1) * LV_STGF;
        float* Bs = As + LV_AF;
#pragma unroll
        for (int t = 0; t < 4; t++) {
            int v = tid + t * 256;
            int r = v >> 3, c = v & 7;
            int row = mBase + r; if (row >= Mout) row = Mout - 1;
            cp16(As + r * ASTR + c * 4, Hin + (size_t)row * 512 + kc * 32 + c * 4);
        }
#pragma unroll
        for (int t = 0; t < 5; t++) {
            int v = tid + t * 256;
            int kr = v / 80, c4 = v - kr * 80;
            cp16(Bs + kr * BSTR2 + c4 * 4,
                 g_Wk + (size_t)(kc * 16 + kr) * 2560 + p0 * 2 + c4 * 4);
        }
        CP_COMMIT();
    };

    load_chunk(0);
    for (int i = 0; i < 16; i++) {
        if (i + 1 < 16) { load_chunk(i + 1); CP_WAIT1(); } else { CP_WAIT0(); }
        __syncthreads();
        const float* As = dsm + (i & 1) * LV_STGF;
        const float* Bs = As + LV_AF;
#pragma unroll
        for (int ks = 0; ks < 4; ks++) {
            uint32_t a[2][4];
#pragma unroll
            for (int ma = 0; ma < 2; ma++) {
                const float* ap = As + (wm * 32 + ma * 16 + qr) * ASTR + ks * 8 + qc;
                a[ma][0] = __float_as_uint(ap[0]);
                a[ma][1] = __float_as_uint(ap[8 * ASTR]);
                a[ma][2] = __float_as_uint(ap[4]);
                a[ma][3] = __float_as_uint(ap[8 * ASTR + 4]);
            }
            const float* brow = Bs + (ks * 4 + qc) * BSTR2;
#pragma unroll
            for (int na = 0; na < 10; na++) {
                int col = (na >> 1) * 32 + wn * 16 + (na & 1) * 8 + qr;
                float2 bf = *(const float2*)(brow + col * 2);
                uint32_t b0 = __float_as_uint(bf.x);
                uint32_t b1 = __float_as_uint(bf.y);
                mma_tf32(acc[0][na], a[0], b0, b1);
                mma_tf32(acc[1][na], a[1], b0, b1);
            }
        }
        __syncthreads();
    }

#pragma unroll
    for (int ma = 0; ma < 2; ma++) {
#pragma unroll
        for (int eh = 0; eh < 2; eh++) {
            int row = mBase + wm * 32 + ma * 16 + qr + eh * 8;
            if (row < Mout) {
#pragma unroll
                for (int na = 0; na < 2; na++) {
                    int jj = wn * 16 + na * 8 + qc * 2;
                    float2 cl = *(const float2*)(Cin + (size_t)row * 512 + c0 + jj);
                    float2 cr = *(const float2*)(Cin + (size_t)row * 512 + 256 + c0 + jj);
                    float hv[2], cv[2];
#pragma unroll
                    for (int e = 0; e < 2; e++) {
                        int bi_ = jj + e;
                        float fl = sigm(acc[ma][0 * 2 + na][eh * 2 + e] + s_bias[0 * 32 + bi_]);
                        float fr = sigm(acc[ma][1 * 2 + na][eh * 2 + e] + s_bias[1 * 32 + bi_]);
                        float ig = sigm(acc[ma][2 * 2 + na][eh * 2 + e] + s_bias[2 * 32 + bi_]);
                        float og = sigm(acc[ma][3 * 2 + na][eh * 2 + e] + s_bias[3 * 32 + bi_]);
                        float cc = tanhf(acc[ma][4 * 2 + na][eh * 2 + e] + s_bias[4 * 32 + bi_]);
                        float clv = (e == 0) ? cl.x : cl.y;
                        float crv = (e == 0) ? cr.x : cr.y;
                        float cn = fl * clv + fr * crv + ig * cc;
                        cv[e] = cn;
                        hv[e] = rnd_tf32(og * tanhf(cn));
                    }
                    *(float2*)(Hout + (size_t)row * 256 + c0 + jj) = make_float2(hv[0], hv[1]);
                    *(float2*)(Cout + (size_t)row * 256 + c0 + jj) = make_float2(cv[0], cv[1]);
                }
            }
        }
    }
}

// ================= LEAF KERNEL — R11 verbatim =================
#define BSTRL 136
#define LF_AF (128 * ASTR)          // 4608
#define LF_BF (32 * BSTRL)          // 4352
#define LF_STGF (LF_AF + LF_BF)     // 8960
#define LF_SMEM (2 * LF_STGF * 4)   // 71680

__global__ __launch_bounds__(256, 2) void leaf_fused(const int* __restrict__ ids,
                                                     const float* __restrict__ emb,
                                                     const float* __restrict__ bp,
                                                     float* __restrict__ Hout,
                                                     float* __restrict__ Cout) {
    extern __shared__ float dsm[];
    __shared__ int s_ids[128];
    __shared__ float s_bp[128];
    const int tid = threadIdx.x, wid = tid >> 5, lane = tid & 31;
    const int qr = lane >> 2, qc = lane & 3;
    const int wm = wid >> 1, wn = wid & 1;
    const int mBase = blockIdx.x * 128;
    const int nBase = blockIdx.y * 128;

    if (tid < 128) {
        s_ids[tid] = ids[mBase + tid];
        s_bp[tid] = bp[nBase + tid];
    }
    __syncthreads();

    float acc[2][8][4];
#pragma unroll
    for (int a = 0; a < 2; a++)
#pragma unroll
        for (int b = 0; b < 8; b++)
#pragma unroll
            for (int e = 0; e < 4; e++) acc[a][b][e] = 0.f;

    auto load_chunk = [&](int kc) {
        float* As = dsm + (kc & 1) * LF_STGF;
        float* Bs = As + LF_AF;
#pragma unroll
        for (int t = 0; t < 4; t++) {
            int v = tid + t * 256;
            int r = v >> 3, c = v & 7;
            cp16(As + r * ASTR + c * 4, emb + (size_t)s_ids[r] * 256 + kc * 32 + c * 4);
        }
#pragma unroll
        for (int t = 0; t < 4; t++) {
            int v = tid + t * 256;
            int kr = v >> 5, c4 = v & 31;
            cp16(Bs + kr * BSTRL + c4 * 4, g_WpK + (size_t)(kc * 32 + kr) * 256 + nBase + c4 * 4);
        }
        CP_COMMIT();
    };

    load_chunk(0);
    for (int i = 0; i < 8; i++) {
        if (i + 1 < 8) { load_chunk(i + 1); CP_WAIT1(); } else { CP_WAIT0(); }
        __syncthreads();
        const float* As = dsm + (i & 1) * LF_STGF;
        const float* Bs = As + LF_AF;
#pragma unroll
        for (int ks = 0; ks < 4; ks++) {
            uint32_t a[2][4];
#pragma unroll
            for (int ma = 0; ma < 2; ma++) {
                const float* ap = As + (wm * 32 + ma * 16 + qr) * ASTR + ks * 8 + qc;
                a[ma][0] = __float_as_uint(rnd_tf32(ap[0]));
                a[ma][1] = __float_as_uint(rnd_tf32(ap[8 * ASTR]));
                a[ma][2] = __float_as_uint(rnd_tf32(ap[4]));
                a[ma][3] = __float_as_uint(rnd_tf32(ap[8 * ASTR + 4]));
            }
            const float* brow = Bs + (ks * 8 + qc) * BSTRL;
#pragma unroll
            for (int na = 0; na < 8; na++) {
                int col = wn * 64 + na * 8 + qr;
                uint32_t b0 = __float_as_uint(brow[col]);
                uint32_t b1 = __float_as_uint(brow[4 * BSTRL + col]);
                mma_tf32(acc[0][na], a[0], b0, b1);
                mma_tf32(acc[1][na], a[1], b0, b1);
            }
        }
        __syncthreads();
    }

#pragma unroll
    for (int ma = 0; ma < 2; ma++) {
#pragma unroll
        for (int eh = 0; eh < 2; eh++) {
            int row = mBase + wm * 32 + ma * 16 + qr + eh * 8;
#pragma unroll
            for (int na = 0; na < 8; na++) {
                int cl = wn * 64 + na * 8 + qc * 2;
                float h0 = acc[ma][na][eh * 2 + 0] + s_bp[cl + 0];
                float h1 = acc[ma][na][eh * 2 + 1] + s_bp[cl + 1];
                *(float2*)(Hout + (size_t)row * 256 + nBase + cl) =
                    make_float2(rnd_tf32(h0), rnd_tf32(h1));
                *(float2*)(Cout + (size_t)row * 256 + nBase + cl) =
                    make_float2(tanhf(h0), tanhf(h1));
            }
        }
    }
}

// ================= PERSISTENT SMALL-LEVELS KERNEL — 3-stage ring =================
#define SL_GRID 128
#define SL_AF (64 * ASTR)           // 2304
#define SL_BF (16 * BSTR2)          // 5248
#define SL_STGF (SL_AF + SL_BF)     // 7552
#define SL_SMEM (3 * SL_STGF * 4)   // 90624

__global__ __launch_bounds__(256, 1) void small_levels(float* __restrict__ inH0,
                                                       float* __restrict__ inC0,
                                                       float* __restrict__ outH0,
                                                       float* __restrict__ outC0,
                                                       const float* __restrict__ Wcls,
                                                       const float* __restrict__ bcls,
                                                       float* __restrict__ out) {
    extern __shared__ float dsm[];
    __shared__ float s_bias[160];
    const int tid = threadIdx.x, wid = tid >> 5, lane = tid & 31;
    const int qr = lane >> 2, qc = lane & 3;
    const int wm = wid >> 1, wn = wid & 1;

    unsigned gen = 0;
    if (tid == 0) gen = *(volatile unsigned*)&g_bar_gen;

    float* inH = inH0;  float* inC = inC0;
    float* outH = outH0; float* outC = outC0;

    int cur = 4096;
    while (cur > 16) {
        const int Mout = cur >> 1;
        const int mtiles = (Mout + 63) >> 6;
        const int nt = mtiles * 8;
        for (int t = blockIdx.x; t < nt; t += SL_GRID) {
            const int grp = t / mtiles;
            const int mtile = t - grp * mtiles;
            const int p0 = grp * 160, c0 = grp * 32;
            const int mBase = mtile * 64;

            for (int i = tid; i < 160; i += 256) s_bias[i] = g_bt[p0 + i];

            float acc[10][4];
#pragma unroll
            for (int b = 0; b < 10; b++)
#pragma unroll
                for (int e = 0; e < 4; e++) acc[b][e] = 0.f;

            auto load_chunk = [&](int kc) {
                float* As = dsm + (kc % 3) * SL_STGF;
                float* Bs = As + SL_AF;
#pragma unroll
                for (int tt = 0; tt < 2; tt++) {
                    int v = tid + tt * 256;
                    int r = v >> 3, c = v & 7;
                    int row = mBase + r; if (row >= Mout) row = Mout - 1;
                    cp16(As + r * ASTR + c * 4, inH + (size_t)row * 512 + kc * 32 + c * 4);
                }
#pragma unroll
                for (int tt = 0; tt < 5; tt++) {
                    int v = tid + tt * 256;
                    int kr = v / 80, c4 = v - kr * 80;
                    cp16(Bs + kr * BSTR2 + c4 * 4,
                         g_Wk + (size_t)(kc * 16 + kr) * 2560 + p0 * 2 + c4 * 4);
                }
                CP_COMMIT();
            };

            // 3-stage pipeline: stage i%3 computed while i+1, i+2 load.
            load_chunk(0); load_chunk(1);
            for (int i = 0; i < 16; i++) {
                if (i + 2 < 16) { load_chunk(i + 2); CP_WAIT2(); }
                else if (i + 1 < 16) { CP_WAIT1(); }
                else { CP_WAIT0(); }
                __syncthreads();
                const float* As = dsm + (i % 3) * SL_STGF;
                const float* Bs = As + SL_AF;
#pragma unroll
                for (int ks = 0; ks < 4; ks++) {
                    uint32_t a[4];
                    const float* ap = As + (wm * 16 + qr) * ASTR + ks * 8 + qc;
                    a[0] = __float_as_uint(ap[0]);
                    a[1] = __float_as_uint(ap[8 * ASTR]);
                    a[2] = __float_as_uint(ap[4]);
                    a[3] = __float_as_uint(ap[8 * ASTR + 4]);
                    const float* brow = Bs + (ks * 4 + qc) * BSTR2;
#pragma unroll
                    for (int na = 0; na < 10; na++) {
                        int col = (na >> 1) * 32 + wn * 16 + (na & 1) * 8 + qr;
                        float2 bf = *(const float2*)(brow + col * 2);
                        mma_tf32(acc[na], a, __float_as_uint(bf.x), __float_as_uint(bf.y));
                    }
                }
                __syncthreads();
            }

#pragma unroll
            for (int eh = 0; eh < 2; eh++) {
                int row = mBase + wm * 16 + qr + eh * 8;
                if (row < Mout) {
#pragma unroll
                    for (int na = 0; na < 2; na++) {
                        int jj = wn * 16 + na * 8 + qc * 2;
                        float2 cl = *(const float2*)(inC + (size_t)row * 512 + c0 + jj);
                        float2 cr = *(const float2*)(inC + (size_t)row * 512 + 256 + c0 + jj);
                        float hv[2], cv[2];
#pragma unroll
                        for (int e = 0; e < 2; e++) {
                            int bi_ = jj + e;
                            float fl = sigm(acc[0 * 2 + na][eh * 2 + e] + s_bias[0 * 32 + bi_]);
                            float fr = sigm(acc[1 * 2 + na][eh * 2 + e] + s_bias[1 * 32 + bi_]);
                            float ig = sigm(acc[2 * 2 + na][eh * 2 + e] + s_bias[2 * 32 + bi_]);
                            float og = sigm(acc[3 * 2 + na][eh * 2 + e] + s_bias[3 * 32 + bi_]);
                            float cc = tanhf(acc[4 * 2 + na][eh * 2 + e] + s_bias[4 * 32 + bi_]);
                            float clv = (e == 0) ? cl.x : cl.y;
                            float crv = (e == 0) ? cr.x : cr.y;
                            float cn = fl * clv + fr * crv + ig * cc;
                            cv[e] = cn;
                            hv[e] = rnd_tf32(og * tanhf(cn));
                        }
                        *(float2*)(outH + (size_t)row * 256 + c0 + jj) = make_float2(hv[0], hv[1]);
                        *(float2*)(outC + (size_t)row * 256 + c0 + jj) = make_float2(cv[0], cv[1]);
                    }
                }
            }
            __syncthreads();
        }

        // -------- grid-wide barrier --------
        __threadfence();
        __syncthreads();
        if (tid == 0) {
            unsigned arrived = atomicAdd(&g_bar_cnt, 1u);
            if (arrived == SL_GRID - 1) {
                g_bar_cnt = 0;
                __threadfence();
                atomicAdd(&g_bar_gen, 1u);
                gen++;
            } else {
                unsigned cg;
                do {
                    __nanosleep(64);
                    asm volatile("ld.acquire.gpu.u32 %0, [%1];" : "=r"(cg) : "l"(&g_bar_gen) : "memory");
                } while (cg == gen);
                gen = cg;
                __threadfence();
            }
        }
        __syncthreads();

        float* th = inH; inH = outH; outH = th;
        float* tc = inC; inC = outC; outC = tc;
        cur = Mout;
    }

    // classifier on root H — CTA 0
    if (blockIdx.x == 0 && tid < BVAL * 2) {
        int b = tid >> 1, cx = tid & 1;
        float sum = bcls[cx];
        const float* h = inH + (size_t)b * HVAL;
        for (int k = 0; k < HVAL; k++) sum += h[k] * Wcls[k * 2 + cx];
        out[b * 2 + cx] = sum;
    }
}

// ---------------- launch ----------------
extern "C" void kernel_launch(void* const* d_in, const int* in_sizes, int n_in,
                              void* d_out, int out_size) {
    const int*   leaf_ids = (const int*)d_in[0];
    const float* emb  = (const float*)d_in[1];
    const float* Wp   = (const float*)d_in[2];
    const float* bp   = (const float*)d_in[3];
    const float* Wfl  = (const float*)d_in[4];
    const float* bfl  = (const float*)d_in[5];
    const float* Wfr  = (const float*)d_in[6];
    const float* bfr  = (const float*)d_in[7];
    const float* Wi   = (const float*)d_in[8];
    const float* bi   = (const float*)d_in[9];
    const float* Wo   = (const float*)d_in[10];
    const float* bo   = (const float*)d_in[11];
    const float* Wc   = (const float*)d_in[12];
    const float* bc   = (const float*)d_in[13];
    const float* Wcls = (const float*)d_in[14];
    const float* bcls = (const float*)d_in[15];
    float* out = (float*)d_out;

    float *Ah, *Ac, *Bh, *Bc;
    cudaGetSymbolAddress((void**)&Ah, g_bufA_h);
    cudaGetSymbolAddress((void**)&Ac, g_bufA_c);
    cudaGetSymbolAddress((void**)&Bh, g_bufB_h);
    cudaGetSymbolAddress((void**)&Bc, g_bufB_c);

    cudaFuncSetAttribute(level_fused,  cudaFuncAttributeMaxDynamicSharedMemorySize, LV_SMEM);
    cudaFuncSetAttribute(leaf_fused,   cudaFuncAttributeMaxDynamicSharedMemorySize, LF_SMEM);
    cudaFuncSetAttribute(small_levels, cudaFuncAttributeMaxDynamicSharedMemorySize, SL_SMEM);

    pack_weights<<<256, 256>>>(Wp, Wfl, Wfr, Wi, Wo, Wc, bfl, bfr, bi, bo, bc);

    leaf_fused<<<dim3(NODES0 / 128, 2), 256, LF_SMEM>>>(leaf_ids, emb, bp, Ah, Ac);

    float *inH = Ah, *inC = Ac, *outH = Bh, *outC = Bc;
    int cur = NODES0;
    while (cur > 4096) {
        int Mout = cur >> 1;
        dim3 grid(Mout / 128, 8);
        level_fused<<<grid, 256, LV_SMEM>>>(inH, inC, outH, outC, Mout);
        float* t;
        t = inH; inH = outH; outH = t;
        t = inC; inC = outC; outC = t;
        cur = Mout;
    }

    small_levels<<<SL_GRID, 256, SL_SMEM>>>(inH, inC, outH, outC, Wcls, bcls, out);
}